// round 13
// baseline (speedup 1.0000x reference)
#include <cuda_runtime.h>

#define EPS    1e-5f
#define V_DIM  32
#define D_DIM  128
#define NPER   8           // n-units (16KB each) per CTA, processed 4 at a time

// ---------------------------------------------------------------------------
// R12 structure with finer CTA granule (NPER 16 -> 8, grid 2048 -> 4096):
// thinner waves shrink the tail quantum further (granule trend: 32->16 won
// ~1us). 1024-thread CTA = 32 warps; warp w owns variable v = w. Each CTA
// iteration writes a CONTIGUOUS 64KB block (4 n-units) — dense CTA write
// footprint is what makes evict-first stores win (R4/R6 vs R5/R8 evidence).
// Lanes hold W/b/gamma/beta[v, lane*4..+3] in registers; warp computes per-v
// stats once via shuffles (analytic LayerNorm — no per-row reduction):
//   h = x*W + b ; mu = x*Wbar + bbar ; var = x^2 VarW + 2x Cov + Varb
// ---------------------------------------------------------------------------
__global__ void __launch_bounds__(1024, 1)
ve_kernel(const float* __restrict__ x,
          const float* __restrict__ W,
          const float* __restrict__ b,
          const float* __restrict__ gamma,
          const float* __restrict__ beta,
          float* __restrict__ out) {
    int v    = threadIdx.x >> 5;     // warp id = variable index
    int lane = threadIdx.x & 31;

    int t = v * 32 + lane;           // [V, D/4] table index
    float4 w4 = __ldg(reinterpret_cast<const float4*>(W)     + t);
    float4 b4 = __ldg(reinterpret_cast<const float4*>(b)     + t);
    float4 g4 = __ldg(reinterpret_cast<const float4*>(gamma) + t);
    float4 e4 = __ldg(reinterpret_cast<const float4*>(beta)  + t);

    // ---- per-v stats via butterfly reductions ----
    float sw = w4.x + w4.y + w4.z + w4.w;
    float sb = b4.x + b4.y + b4.z + b4.w;
    #pragma unroll
    for (int off = 16; off > 0; off >>= 1) {
        sw += __shfl_xor_sync(0xFFFFFFFFu, sw, off);
        sb += __shfl_xor_sync(0xFFFFFFFFu, sb, off);
    }
    float Wbar = sw * (1.0f / D_DIM);
    float bbar = sb * (1.0f / D_DIM);

    float wc0 = w4.x - Wbar, wc1 = w4.y - Wbar, wc2 = w4.z - Wbar, wc3 = w4.w - Wbar;
    float bc0 = b4.x - bbar, bc1 = b4.y - bbar, bc2 = b4.z - bbar, bc3 = b4.w - bbar;
    float sww = wc0*wc0 + wc1*wc1 + wc2*wc2 + wc3*wc3;
    float swb = wc0*bc0 + wc1*bc1 + wc2*bc2 + wc3*bc3;
    float sbb = bc0*bc0 + bc1*bc1 + bc2*bc2 + bc3*bc3;
    #pragma unroll
    for (int off = 16; off > 0; off >>= 1) {
        sww += __shfl_xor_sync(0xFFFFFFFFu, sww, off);
        swb += __shfl_xor_sync(0xFFFFFFFFu, swb, off);
        sbb += __shfl_xor_sync(0xFFFFFFFFu, sbb, off);
    }
    float varW = sww * (1.0f / D_DIM);
    float cov2 = swb * (2.0f / D_DIM);   // 2*Cov(W,b)
    float varb = sbb * (1.0f / D_DIM);

    int n0 = blockIdx.x * NPER;
    const float* xp = x + (size_t)n0 * V_DIM + v;               // x[n*V + v]
    float4* orow = reinterpret_cast<float4*>(out)
                 + ((size_t)n0 * V_DIM + v) * 32 + lane;        // row base
    const int UNIT4 = V_DIM * 32;                                // float4s per n-unit

    #pragma unroll
    for (int i = 0; i < NPER / 4; i++) {
        // front-batch 4 independent x loads
        float xv0 = __ldg(xp + (size_t)(4 * i)     * V_DIM);
        float xv1 = __ldg(xp + (size_t)(4 * i + 1) * V_DIM);
        float xv2 = __ldg(xp + (size_t)(4 * i + 2) * V_DIM);
        float xv3 = __ldg(xp + (size_t)(4 * i + 3) * V_DIM);

        float rs0 = rsqrtf(fmaf(xv0, fmaf(xv0, varW, cov2), varb) + EPS);
        float rs1 = rsqrtf(fmaf(xv1, fmaf(xv1, varW, cov2), varb) + EPS);
        float rs2 = rsqrtf(fmaf(xv2, fmaf(xv2, varW, cov2), varb) + EPS);
        float rs3 = rsqrtf(fmaf(xv3, fmaf(xv3, varW, cov2), varb) + EPS);
        float nm0 = -fmaf(xv0, Wbar, bbar) * rs0;
        float nm1 = -fmaf(xv1, Wbar, bbar) * rs1;
        float nm2 = -fmaf(xv2, Wbar, bbar) * rs2;
        float nm3 = -fmaf(xv3, Wbar, bbar) * rs3;

        #define ROW_OUT(o, xv, rs, nm)                                        \
        {                                                                     \
            { float h = fmaf(w4.x, xv, b4.x); float y = fmaf(h, rs, nm);      \
              o.x = fmaxf(fmaf(g4.x, y, e4.x), 0.0f); }                       \
            { float h = fmaf(w4.y, xv, b4.y); float y = fmaf(h, rs, nm);      \
              o.y = fmaxf(fmaf(g4.y, y, e4.y), 0.0f); }                       \
            { float h = fmaf(w4.z, xv, b4.z); float y = fmaf(h, rs, nm);      \
              o.z = fmaxf(fmaf(g4.z, y, e4.z), 0.0f); }                       \
            { float h = fmaf(w4.w, xv, b4.w); float y = fmaf(h, rs, nm);      \
              o.w = fmaxf(fmaf(g4.w, y, e4.w), 0.0f); }                       \
        }

        float4 o0; ROW_OUT(o0, xv0, rs0, nm0);
        float4 o1; ROW_OUT(o1, xv1, rs1, nm1);
        __stcs(orow + (size_t)(4 * i)     * UNIT4, o0);
        __stcs(orow + (size_t)(4 * i + 1) * UNIT4, o1);
        float4 o2; ROW_OUT(o2, xv2, rs2, nm2);
        float4 o3; ROW_OUT(o3, xv3, rs3, nm3);
        __stcs(orow + (size_t)(4 * i + 2) * UNIT4, o2);
        __stcs(orow + (size_t)(4 * i + 3) * UNIT4, o3);

        #undef ROW_OUT
    }
}

// ---------------------------------------------------------------------------
extern "C" void kernel_launch(void* const* d_in, const int* in_sizes, int n_in,
                              void* d_out, int out_size) {
    const float* x     = (const float*)d_in[0];
    const float* W     = (const float*)d_in[1];
    const float* b     = (const float*)d_in[2];
    const float* gamma = (const float*)d_in[3];
    const float* beta  = (const float*)d_in[4];
    float* out = (float*)d_out;

    // n-units of 16KB = out_size / (V*D) = 32768 ; blocks = 32768/NPER = 4096
    int n_units = out_size / (V_DIM * D_DIM);
    int blocks  = n_units / NPER;

    ve_kernel<<<blocks, 1024>>>(x, W, b, gamma, beta, out);
}

// round 14
// speedup vs baseline: 1.1800x; 1.1800x over previous
#include <cuda_runtime.h>

#define EPS    1e-5f
#define V_DIM  32
#define D_DIM  128
#define NPER   16          // n-units (16KB each) per CTA

// ---------------------------------------------------------------------------
// R12 granule (NPER=16, grid=2048) but with 512-thread CTAs and 2 CTAs/SM:
// co-residency hides each CTA's prologue/drain behind the sibling CTA's
// store stream (R13 showed exposed prologue is the cost at fine granules).
// 16 warps; warp w owns variables v0=2w, v1=2w+1 (both table sets in regs).
// Each CTA iteration still writes a CONTIGUOUS 16KB n-unit (dense footprint
// = the proven evict-first condition), 2 units per batch for store MLP.
// Analytic LayerNorm (no per-row reduction):
//   h = x*W + b ; mu = x*Wbar + bbar ; var = x^2 VarW + 2x Cov + Varb
// ---------------------------------------------------------------------------
__global__ void __launch_bounds__(512, 2)
ve_kernel(const float* __restrict__ x,
          const float* __restrict__ W,
          const float* __restrict__ b,
          const float* __restrict__ gamma,
          const float* __restrict__ beta,
          float* __restrict__ out) {
    int w    = threadIdx.x >> 5;     // warp id 0..15
    int lane = threadIdx.x & 31;
    int v0   = 2 * w;
    int v1   = 2 * w + 1;

    // ---- load both table sets ----
    int t0 = v0 * 32 + lane;
    int t1 = v1 * 32 + lane;
    float4 w40 = __ldg(reinterpret_cast<const float4*>(W)     + t0);
    float4 b40 = __ldg(reinterpret_cast<const float4*>(b)     + t0);
    float4 g40 = __ldg(reinterpret_cast<const float4*>(gamma) + t0);
    float4 e40 = __ldg(reinterpret_cast<const float4*>(beta)  + t0);
    float4 w41 = __ldg(reinterpret_cast<const float4*>(W)     + t1);
    float4 b41 = __ldg(reinterpret_cast<const float4*>(b)     + t1);
    float4 g41 = __ldg(reinterpret_cast<const float4*>(gamma) + t1);
    float4 e41 = __ldg(reinterpret_cast<const float4*>(beta)  + t1);

    // ---- per-v stats via butterfly reductions (both v's at once) ----
    float sw0 = w40.x + w40.y + w40.z + w40.w;
    float sb0 = b40.x + b40.y + b40.z + b40.w;
    float sw1 = w41.x + w41.y + w41.z + w41.w;
    float sb1 = b41.x + b41.y + b41.z + b41.w;
    #pragma unroll
    for (int off = 16; off > 0; off >>= 1) {
        sw0 += __shfl_xor_sync(0xFFFFFFFFu, sw0, off);
        sb0 += __shfl_xor_sync(0xFFFFFFFFu, sb0, off);
        sw1 += __shfl_xor_sync(0xFFFFFFFFu, sw1, off);
        sb1 += __shfl_xor_sync(0xFFFFFFFFu, sb1, off);
    }
    float Wbar0 = sw0 * (1.0f / D_DIM), bbar0 = sb0 * (1.0f / D_DIM);
    float Wbar1 = sw1 * (1.0f / D_DIM), bbar1 = sb1 * (1.0f / D_DIM);

    float a0,a1,a2,a3, c0,c1,c2,c3;
    a0 = w40.x - Wbar0; a1 = w40.y - Wbar0; a2 = w40.z - Wbar0; a3 = w40.w - Wbar0;
    c0 = b40.x - bbar0; c1 = b40.y - bbar0; c2 = b40.z - bbar0; c3 = b40.w - bbar0;
    float sww0 = a0*a0 + a1*a1 + a2*a2 + a3*a3;
    float swb0 = a0*c0 + a1*c1 + a2*c2 + a3*c3;
    float sbb0 = c0*c0 + c1*c1 + c2*c2 + c3*c3;
    a0 = w41.x - Wbar1; a1 = w41.y - Wbar1; a2 = w41.z - Wbar1; a3 = w41.w - Wbar1;
    c0 = b41.x - bbar1; c1 = b41.y - bbar1; c2 = b41.z - bbar1; c3 = b41.w - bbar1;
    float sww1 = a0*a0 + a1*a1 + a2*a2 + a3*a3;
    float swb1 = a0*c0 + a1*c1 + a2*c2 + a3*c3;
    float sbb1 = c0*c0 + c1*c1 + c2*c2 + c3*c3;
    #pragma unroll
    for (int off = 16; off > 0; off >>= 1) {
        sww0 += __shfl_xor_sync(0xFFFFFFFFu, sww0, off);
        swb0 += __shfl_xor_sync(0xFFFFFFFFu, swb0, off);
        sbb0 += __shfl_xor_sync(0xFFFFFFFFu, sbb0, off);
        sww1 += __shfl_xor_sync(0xFFFFFFFFu, sww1, off);
        swb1 += __shfl_xor_sync(0xFFFFFFFFu, swb1, off);
        sbb1 += __shfl_xor_sync(0xFFFFFFFFu, sbb1, off);
    }
    float varW0 = sww0 * (1.0f / D_DIM), cov20 = swb0 * (2.0f / D_DIM),
          varb0 = sbb0 * (1.0f / D_DIM);
    float varW1 = sww1 * (1.0f / D_DIM), cov21 = swb1 * (2.0f / D_DIM),
          varb1 = sbb1 * (1.0f / D_DIM);

    int n0 = blockIdx.x * NPER;
    const float* xp0 = x + (size_t)n0 * V_DIM + v0;
    float4* base = reinterpret_cast<float4*>(out)
                 + ((size_t)n0 * V_DIM + v0) * 32 + lane;   // row of v0, unit n0
    const int UNIT4 = V_DIM * 32;                            // float4s per n-unit

    #define ROW_OUT(o, xv, rs, nm, w4, b4, g4, e4)                            \
    {                                                                         \
        { float h = fmaf(w4.x, xv, b4.x); float y = fmaf(h, rs, nm);          \
          o.x = fmaxf(fmaf(g4.x, y, e4.x), 0.0f); }                           \
        { float h = fmaf(w4.y, xv, b4.y); float y = fmaf(h, rs, nm);          \
          o.y = fmaxf(fmaf(g4.y, y, e4.y), 0.0f); }                           \
        { float h = fmaf(w4.z, xv, b4.z); float y = fmaf(h, rs, nm);          \
          o.z = fmaxf(fmaf(g4.z, y, e4.z), 0.0f); }                           \
        { float h = fmaf(w4.w, xv, b4.w); float y = fmaf(h, rs, nm);          \
          o.w = fmaxf(fmaf(g4.w, y, e4.w), 0.0f); }                           \
    }

    #pragma unroll 2
    for (int i = 0; i < NPER / 2; i++) {
        // front-batch x loads for 2 units x 2 variables
        float xa0 = __ldg(xp0 + (size_t)(2 * i)     * V_DIM);      // unit i0, v0
        float xa1 = __ldg(xp0 + (size_t)(2 * i)     * V_DIM + 1);  // unit i0, v1
        float xb0 = __ldg(xp0 + (size_t)(2 * i + 1) * V_DIM);      // unit i1, v0
        float xb1 = __ldg(xp0 + (size_t)(2 * i + 1) * V_DIM + 1);  // unit i1, v1

        // ---- unit 2i ----
        {
            float rsA = rsqrtf(fmaf(xa0, fmaf(xa0, varW0, cov20), varb0) + EPS);
            float nmA = -fmaf(xa0, Wbar0, bbar0) * rsA;
            float rsB = rsqrtf(fmaf(xa1, fmaf(xa1, varW1, cov21), varb1) + EPS);
            float nmB = -fmaf(xa1, Wbar1, bbar1) * rsB;
            float4 oA; ROW_OUT(oA, xa0, rsA, nmA, w40, b40, g40, e40);
            float4 oB; ROW_OUT(oB, xa1, rsB, nmB, w41, b41, g41, e41);
            float4* u = base + (size_t)(2 * i) * UNIT4;
            __stcs(u,      oA);       // row v0
            __stcs(u + 32, oB);       // row v1 (next 512B)
        }
        // ---- unit 2i+1 ----
        {
            float rsA = rsqrtf(fmaf(xb0, fmaf(xb0, varW0, cov20), varb0) + EPS);
            float nmA = -fmaf(xb0, Wbar0, bbar0) * rsA;
            float rsB = rsqrtf(fmaf(xb1, fmaf(xb1, varW1, cov21), varb1) + EPS);
            float nmB = -fmaf(xb1, Wbar1, bbar1) * rsB;
            float4 oA; ROW_OUT(oA, xb0, rsA, nmA, w40, b40, g40, e40);
            float4 oB; ROW_OUT(oB, xb1, rsB, nmB, w41, b41, g41, e41);
            float4* u = base + (size_t)(2 * i + 1) * UNIT4;
            __stcs(u,      oA);
            __stcs(u + 32, oB);
        }
    }
    #undef ROW_OUT
}

// ---------------------------------------------------------------------------
extern "C" void kernel_launch(void* const* d_in, const int* in_sizes, int n_in,
                              void* d_out, int out_size) {
    const float* x     = (const float*)d_in[0];
    const float* W     = (const float*)d_in[1];
    const float* b     = (const float*)d_in[2];
    const float* gamma = (const float*)d_in[3];
    const float* beta  = (const float*)d_in[4];
    float* out = (float*)d_out;

    // n-units of 16KB = out_size / (V*D) = 32768 ; blocks = 32768/NPER = 2048
    int n_units = out_size / (V_DIM * D_DIM);
    int blocks  = n_units / NPER;

    ve_kernel<<<blocks, 512>>>(x, W, b, gamma, beta, out);
}

// round 15
// speedup vs baseline: 1.2182x; 1.0324x over previous
#include <cuda_runtime.h>

#define EPS    1e-5f
#define V_DIM  32
#define D_DIM  128
#define NPER   8           // n-units (16KB each) per CTA

// ---------------------------------------------------------------------------
// R14 winner (512-thread CTAs, 2 CTAs/SM co-residency hides CTA-boundary
// prologue/drain) with finer granule NPER 16 -> 8 (grid 4096): smaller tail
// quantum / per-wave imbalance now that prologues are hidden by the sibling
// CTA (the R13 failure mode no longer applies).
// 16 warps; warp w owns variables v0=2w, v1=2w+1 (both table sets in regs).
// Each CTA iteration writes CONTIGUOUS 16KB n-units (dense footprint = the
// proven evict-first condition), 2 units per batch for store MLP.
// Analytic LayerNorm (no per-row reduction):
//   h = x*W + b ; mu = x*Wbar + bbar ; var = x^2 VarW + 2x Cov + Varb
// ---------------------------------------------------------------------------
__global__ void __launch_bounds__(512, 2)
ve_kernel(const float* __restrict__ x,
          const float* __restrict__ W,
          const float* __restrict__ b,
          const float* __restrict__ gamma,
          const float* __restrict__ beta,
          float* __restrict__ out) {
    int w    = threadIdx.x >> 5;     // warp id 0..15
    int lane = threadIdx.x & 31;
    int v0   = 2 * w;
    int v1   = 2 * w + 1;

    // ---- load both table sets ----
    int t0 = v0 * 32 + lane;
    int t1 = v1 * 32 + lane;
    float4 w40 = __ldg(reinterpret_cast<const float4*>(W)     + t0);
    float4 b40 = __ldg(reinterpret_cast<const float4*>(b)     + t0);
    float4 g40 = __ldg(reinterpret_cast<const float4*>(gamma) + t0);
    float4 e40 = __ldg(reinterpret_cast<const float4*>(beta)  + t0);
    float4 w41 = __ldg(reinterpret_cast<const float4*>(W)     + t1);
    float4 b41 = __ldg(reinterpret_cast<const float4*>(b)     + t1);
    float4 g41 = __ldg(reinterpret_cast<const float4*>(gamma) + t1);
    float4 e41 = __ldg(reinterpret_cast<const float4*>(beta)  + t1);

    // ---- per-v stats via butterfly reductions (both v's at once) ----
    float sw0 = w40.x + w40.y + w40.z + w40.w;
    float sb0 = b40.x + b40.y + b40.z + b40.w;
    float sw1 = w41.x + w41.y + w41.z + w41.w;
    float sb1 = b41.x + b41.y + b41.z + b41.w;
    #pragma unroll
    for (int off = 16; off > 0; off >>= 1) {
        sw0 += __shfl_xor_sync(0xFFFFFFFFu, sw0, off);
        sb0 += __shfl_xor_sync(0xFFFFFFFFu, sb0, off);
        sw1 += __shfl_xor_sync(0xFFFFFFFFu, sw1, off);
        sb1 += __shfl_xor_sync(0xFFFFFFFFu, sb1, off);
    }
    float Wbar0 = sw0 * (1.0f / D_DIM), bbar0 = sb0 * (1.0f / D_DIM);
    float Wbar1 = sw1 * (1.0f / D_DIM), bbar1 = sb1 * (1.0f / D_DIM);

    float a0,a1,a2,a3, c0,c1,c2,c3;
    a0 = w40.x - Wbar0; a1 = w40.y - Wbar0; a2 = w40.z - Wbar0; a3 = w40.w - Wbar0;
    c0 = b40.x - bbar0; c1 = b40.y - bbar0; c2 = b40.z - bbar0; c3 = b40.w - bbar0;
    float sww0 = a0*a0 + a1*a1 + a2*a2 + a3*a3;
    float swb0 = a0*c0 + a1*c1 + a2*c2 + a3*c3;
    float sbb0 = c0*c0 + c1*c1 + c2*c2 + c3*c3;
    a0 = w41.x - Wbar1; a1 = w41.y - Wbar1; a2 = w41.z - Wbar1; a3 = w41.w - Wbar1;
    c0 = b41.x - bbar1; c1 = b41.y - bbar1; c2 = b41.z - bbar1; c3 = b41.w - bbar1;
    float sww1 = a0*a0 + a1*a1 + a2*a2 + a3*a3;
    float swb1 = a0*c0 + a1*c1 + a2*c2 + a3*c3;
    float sbb1 = c0*c0 + c1*c1 + c2*c2 + c3*c3;
    #pragma unroll
    for (int off = 16; off > 0; off >>= 1) {
        sww0 += __shfl_xor_sync(0xFFFFFFFFu, sww0, off);
        swb0 += __shfl_xor_sync(0xFFFFFFFFu, swb0, off);
        sbb0 += __shfl_xor_sync(0xFFFFFFFFu, sbb0, off);
        sww1 += __shfl_xor_sync(0xFFFFFFFFu, sww1, off);
        swb1 += __shfl_xor_sync(0xFFFFFFFFu, swb1, off);
        sbb1 += __shfl_xor_sync(0xFFFFFFFFu, sbb1, off);
    }
    float varW0 = sww0 * (1.0f / D_DIM), cov20 = swb0 * (2.0f / D_DIM),
          varb0 = sbb0 * (1.0f / D_DIM);
    float varW1 = sww1 * (1.0f / D_DIM), cov21 = swb1 * (2.0f / D_DIM),
          varb1 = sbb1 * (1.0f / D_DIM);

    int n0 = blockIdx.x * NPER;
    const float* xp0 = x + (size_t)n0 * V_DIM + v0;
    float4* base = reinterpret_cast<float4*>(out)
                 + ((size_t)n0 * V_DIM + v0) * 32 + lane;   // row of v0, unit n0
    const int UNIT4 = V_DIM * 32;                            // float4s per n-unit

    #define ROW_OUT(o, xv, rs, nm, w4, b4, g4, e4)                            \
    {                                                                         \
        { float h = fmaf(w4.x, xv, b4.x); float y = fmaf(h, rs, nm);          \
          o.x = fmaxf(fmaf(g4.x, y, e4.x), 0.0f); }                           \
        { float h = fmaf(w4.y, xv, b4.y); float y = fmaf(h, rs, nm);          \
          o.y = fmaxf(fmaf(g4.y, y, e4.y), 0.0f); }                           \
        { float h = fmaf(w4.z, xv, b4.z); float y = fmaf(h, rs, nm);          \
          o.z = fmaxf(fmaf(g4.z, y, e4.z), 0.0f); }                           \
        { float h = fmaf(w4.w, xv, b4.w); float y = fmaf(h, rs, nm);          \
          o.w = fmaxf(fmaf(g4.w, y, e4.w), 0.0f); }                           \
    }

    #pragma unroll 2
    for (int i = 0; i < NPER / 2; i++) {
        // front-batch x loads for 2 units x 2 variables
        float xa0 = __ldg(xp0 + (size_t)(2 * i)     * V_DIM);      // unit i0, v0
        float xa1 = __ldg(xp0 + (size_t)(2 * i)     * V_DIM + 1);  // unit i0, v1
        float xb0 = __ldg(xp0 + (size_t)(2 * i + 1) * V_DIM);      // unit i1, v0
        float xb1 = __ldg(xp0 + (size_t)(2 * i + 1) * V_DIM + 1);  // unit i1, v1

        // ---- unit 2i ----
        {
            float rsA = rsqrtf(fmaf(xa0, fmaf(xa0, varW0, cov20), varb0) + EPS);
            float nmA = -fmaf(xa0, Wbar0, bbar0) * rsA;
            float rsB = rsqrtf(fmaf(xa1, fmaf(xa1, varW1, cov21), varb1) + EPS);
            float nmB = -fmaf(xa1, Wbar1, bbar1) * rsB;
            float4 oA; ROW_OUT(oA, xa0, rsA, nmA, w40, b40, g40, e40);
            float4 oB; ROW_OUT(oB, xa1, rsB, nmB, w41, b41, g41, e41);
            float4* u = base + (size_t)(2 * i) * UNIT4;
            __stcs(u,      oA);       // row v0
            __stcs(u + 32, oB);       // row v1 (next 512B)
        }
        // ---- unit 2i+1 ----
        {
            float rsA = rsqrtf(fmaf(xb0, fmaf(xb0, varW0, cov20), varb0) + EPS);
            float nmA = -fmaf(xb0, Wbar0, bbar0) * rsA;
            float rsB = rsqrtf(fmaf(xb1, fmaf(xb1, varW1, cov21), varb1) + EPS);
            float nmB = -fmaf(xb1, Wbar1, bbar1) * rsB;
            float4 oA; ROW_OUT(oA, xb0, rsA, nmA, w40, b40, g40, e40);
            float4 oB; ROW_OUT(oB, xb1, rsB, nmB, w41, b41, g41, e41);
            float4* u = base + (size_t)(2 * i + 1) * UNIT4;
            __stcs(u,      oA);
            __stcs(u + 32, oB);
        }
    }
    #undef ROW_OUT
}

// ---------------------------------------------------------------------------
extern "C" void kernel_launch(void* const* d_in, const int* in_sizes, int n_in,
                              void* d_out, int out_size) {
    const float* x     = (const float*)d_in[0];
    const float* W     = (const float*)d_in[1];
    const float* b     = (const float*)d_in[2];
    const float* gamma = (const float*)d_in[3];
    const float* beta  = (const float*)d_in[4];
    float* out = (float*)d_out;

    // n-units of 16KB = out_size / (V*D) = 32768 ; blocks = 32768/NPER = 4096
    int n_units = out_size / (V_DIM * D_DIM);
    int blocks  = n_units / NPER;

    ve_kernel<<<blocks, 512>>>(x, W, b, gamma, beta, out);
}